// round 4
// baseline (speedup 1.0000x reference)
#include <cuda_runtime.h>

#define NNODES 16383
#define EMBED 512
#define E4 128          // float4 per H row
#define NLEV 16
#define LEAVES 8192
#define MAXM 4096       // max nodes in an internal level

// ---------------- device scratch (static, no runtime alloc) ----------------
__device__ float4 g_H[NNODES * E4];          // 33.5 MB hidden states
__device__ float4 g_part[8 * MAXM * E4];     // 67 MB split-K partials
__device__ int    g_list[NLEV][MAXM];
__device__ int    g_cnt[NLEV];

// ---------------- schedule kernels ----------------
__global__ void k_zero() {
    if (threadIdx.x < NLEV) g_cnt[threadIdx.x] = 0;
}

__global__ void k_bucket(const int* __restrict__ is_leaf,
                         const int* __restrict__ left) {
    int i = blockIdx.x * blockDim.x + threadIdx.x;
    if (i >= NNODES) return;
    if (is_leaf[i]) return;
    // depth via leftmost-descendant chase (balanced tree: left height = height-1)
    int c = left[i];
    int d = 1;
    while (!is_leaf[c]) { c = left[c]; d++; if (d >= NLEV) break; }
    if (d >= NLEV) d = NLEV - 1;
    int slot = atomicAdd(&g_cnt[d], 1);
    if (slot < MAXM) g_list[d][slot] = i;
}

// ---------------- leaves: H[i] = relu(emb[word[i]]) ----------------
__global__ void k_leaf(const int* __restrict__ is_leaf,
                       const int* __restrict__ word,
                       const float4* __restrict__ emb4) {
    int t = blockIdx.x * blockDim.x + threadIdx.x;
    int node = t >> 7;
    if (node >= NNODES) return;
    if (!is_leaf[node]) return;
    int j = t & 127;
    float4 v = emb4[word[node] * E4 + j];
    v.x = fmaxf(v.x, 0.f); v.y = fmaxf(v.y, 0.f);
    v.z = fmaxf(v.z, 0.f); v.w = fmaxf(v.w, 0.f);
    g_H[node * E4 + j] = v;
}

// ---------------- split-K GEMM partial ----------------
// out_part[z][m][n] = sum over K-chunk z of W[n][k] * pair[m][k]
// pair[m] = concat(H[left[node_m]], H[right[node_m]])
// BM=128, BN=128, BK=16, 256 threads, 8x8 micro-tile.
__global__ __launch_bounds__(256, 2) void k_partial(
    int d, int ZS,
    const int* __restrict__ left, const int* __restrict__ right,
    const float4* __restrict__ W4)
{
    int cnt = g_cnt[d];
    if (cnt == 0) return;
    const int* list = g_list[d];

    int z  = blockIdx.z;
    int n0 = blockIdx.y << 7;           // output-col tile base (0..384)
    int kchunk4 = 256 / ZS;             // float4s per K chunk (64 or 32)
    int aoff4 = (z & ((ZS >> 1) - 1)) * kchunk4;   // within-child col (f4)
    int woff4 = z * kchunk4;                        // within-W col (f4)
    bool useRight = (z >= (ZS >> 1));

    __shared__ float As[16 * 132];
    __shared__ float Bs[16 * 132];
    __shared__ int s_src[128];

    int tid = threadIdx.x;
    int tx = tid & 15, ty = tid >> 4;   // thread tile: n = tx*8, m = ty*8
    int c4  = tid & 3;                  // k-f4 chunk within BK tile
    int row = tid >> 2;                 // 0..63 (row index for loading)
    int mtiles = (cnt + 127) >> 7;

    for (int bm = blockIdx.x; bm < mtiles; bm += gridDim.x) {
        if (tid < 128) {
            int m = bm * 128 + tid;
            int src = 0;
            if (m < cnt) {
                int node = list[m];
                src = useRight ? right[node] : left[node];
            }
            s_src[tid] = src;
        }
        __syncthreads();

        float acc[8][8];
#pragma unroll
        for (int i = 0; i < 8; i++)
#pragma unroll
            for (int j = 0; j < 8; j++) acc[i][j] = 0.f;

        for (int k4 = 0; k4 < kchunk4; k4 += 4) {   // BK = 16 floats
#pragma unroll
            for (int r = 0; r < 2; r++) {
                int mr = row + r * 64;
                float4 va = g_H[s_src[mr] * E4 + aoff4 + k4 + c4];
                As[(c4 * 4 + 0) * 132 + mr] = va.x;
                As[(c4 * 4 + 1) * 132 + mr] = va.y;
                As[(c4 * 4 + 2) * 132 + mr] = va.z;
                As[(c4 * 4 + 3) * 132 + mr] = va.w;
                float4 vb = W4[(n0 + mr) * 256 + woff4 + k4 + c4];
                Bs[(c4 * 4 + 0) * 132 + mr] = vb.x;
                Bs[(c4 * 4 + 1) * 132 + mr] = vb.y;
                Bs[(c4 * 4 + 2) * 132 + mr] = vb.z;
                Bs[(c4 * 4 + 3) * 132 + mr] = vb.w;
            }
            __syncthreads();
#pragma unroll
            for (int kk = 0; kk < 16; kk++) {
                float4 a0 = *(const float4*)&As[kk * 132 + ty * 8];
                float4 a1 = *(const float4*)&As[kk * 132 + ty * 8 + 4];
                float4 b0 = *(const float4*)&Bs[kk * 132 + tx * 8];
                float4 b1 = *(const float4*)&Bs[kk * 132 + tx * 8 + 4];
                float a[8] = {a0.x, a0.y, a0.z, a0.w, a1.x, a1.y, a1.z, a1.w};
                float b[8] = {b0.x, b0.y, b0.z, b0.w, b1.x, b1.y, b1.z, b1.w};
#pragma unroll
                for (int i = 0; i < 8; i++)
#pragma unroll
                    for (int j = 0; j < 8; j++) acc[i][j] += a[i] * b[j];
            }
            __syncthreads();
        }

        float4* pout = g_part + (size_t)z * MAXM * E4;
#pragma unroll
        for (int i = 0; i < 8; i++) {
            int m = bm * 128 + ty * 8 + i;
            if (m < cnt) {
                float4 o0 = make_float4(acc[i][0], acc[i][1], acc[i][2], acc[i][3]);
                float4 o1 = make_float4(acc[i][4], acc[i][5], acc[i][6], acc[i][7]);
                pout[m * E4 + (n0 >> 2) + tx * 2 + 0] = o0;
                pout[m * E4 + (n0 >> 2) + tx * 2 + 1] = o1;
            }
        }
        __syncthreads();
    }
}

// ---------------- combine partials + bias + relu -> H ----------------
__global__ void k_combine(int d, int ZS, const float4* __restrict__ bW4) {
    int cnt = g_cnt[d];
    const int* list = g_list[d];
    int total = cnt * E4;
    for (int idx = blockIdx.x * blockDim.x + threadIdx.x; idx < total;
         idx += gridDim.x * blockDim.x) {
        int m = idx >> 7, j = idx & 127;
        float4 s = g_part[m * E4 + j];
        for (int z = 1; z < ZS; z++) {
            float4 p = g_part[((size_t)z * MAXM + m) * E4 + j];
            s.x += p.x; s.y += p.y; s.z += p.z; s.w += p.w;
        }
        float4 b = bW4[j];
        s.x = fmaxf(s.x + b.x, 0.f);
        s.y = fmaxf(s.y + b.y, 0.f);
        s.z = fmaxf(s.z + b.z, 0.f);
        s.w = fmaxf(s.w + b.w, 0.f);
        g_H[list[m] * E4 + j] = s;
    }
}

// ---------------- small levels (<=32 nodes): warp-per-output ----------------
__global__ __launch_bounds__(256) void k_small(
    int d, const int* __restrict__ left, const int* __restrict__ right,
    const float4* __restrict__ W4, const float* __restrict__ bW)
{
    int cnt = g_cnt[d];
    __shared__ float4 pair[256];   // 1024 floats = [h_l ; h_r]
    int tid = threadIdx.x;
    int lane = tid & 31, w = tid >> 5;
    int n0 = blockIdx.y << 7;      // 128 outputs per block
    float* Hf = (float*)g_H;

    for (int bx = blockIdx.x; bx < cnt; bx += gridDim.x) {
        int node = g_list[d][bx];
        int cl = left[node], cr = right[node];
        __syncthreads();
        pair[tid] = (tid < 128) ? g_H[cl * E4 + tid] : g_H[cr * E4 + tid - 128];
        __syncthreads();
#pragma unroll 1
        for (int o = 0; o < 16; o++) {
            int n = n0 + w * 16 + o;
            const float4* wrow = W4 + n * 256;
            float acc = 0.f;
#pragma unroll
            for (int it = 0; it < 8; it++) {
                float4 wv = wrow[lane + it * 32];
                float4 pv = pair[lane + it * 32];
                acc += wv.x * pv.x + wv.y * pv.y + wv.z * pv.z + wv.w * pv.w;
            }
#pragma unroll
            for (int off = 16; off; off >>= 1)
                acc += __shfl_xor_sync(0xffffffffu, acc, off);
            if (lane == 0)
                Hf[node * EMBED + n] = fmaxf(acc + bW[n], 0.f);
        }
    }
}

// ---------------- logits: out[i][c] = H[i] . P[c] + bP[c] ----------------
__global__ void k_logits(const float4* __restrict__ P4,
                         const float* __restrict__ bP,
                         float* __restrict__ out) {
    int gw = (blockIdx.x * blockDim.x + threadIdx.x) >> 5;
    int lane = threadIdx.x & 31;
    if (gw >= NNODES) return;
    float4 h[4];
#pragma unroll
    for (int i = 0; i < 4; i++) h[i] = g_H[gw * E4 + lane + i * 32];
#pragma unroll
    for (int c = 0; c < 5; c++) {
        float acc = 0.f;
#pragma unroll
        for (int i = 0; i < 4; i++) {
            float4 p = P4[c * E4 + lane + i * 32];
            acc += p.x * h[i].x + p.y * h[i].y + p.z * h[i].z + p.w * h[i].w;
        }
#pragma unroll
        for (int off = 16; off; off >>= 1)
            acc += __shfl_xor_sync(0xffffffffu, acc, off);
        if (lane == 0) out[gw * 5 + c] = acc + bP[c];
    }
}

// ---------------- launch ----------------
extern "C" void kernel_launch(void* const* d_in, const int* in_sizes, int n_in,
                              void* d_out, int out_size) {
    const int*   is_leaf = (const int*)d_in[0];
    const int*   word    = (const int*)d_in[1];
    const int*   left    = (const int*)d_in[2];
    const int*   right   = (const int*)d_in[3];
    const float* emb     = (const float*)d_in[4];
    const float* W       = (const float*)d_in[5];
    const float* bW      = (const float*)d_in[6];
    const float* P       = (const float*)d_in[7];
    const float* bP      = (const float*)d_in[8];
    float* out = (float*)d_out;

    k_zero<<<1, 32>>>();
    k_bucket<<<(NNODES + 255) / 256, 256>>>(is_leaf, left);
    k_leaf<<<(NNODES * 128 + 255) / 256, 256>>>(is_leaf, word, (const float4*)emb);

    for (int d = 1; d <= 13; d++) {
        int cnt = LEAVES >> d;   // expected level size (kernels read actual count)
        if (cnt >= 64) {
            int ZS = (d <= 3) ? 4 : 8;
            int mt = (cnt + 127) / 128; if (mt < 1) mt = 1;
            k_partial<<<dim3(mt, 4, ZS), 256>>>(d, ZS, left, right, (const float4*)W);
            int cb = (cnt * 128 + 255) / 256; if (cb < 1) cb = 1;
            k_combine<<<cb, 256>>>(d, ZS, (const float4*)bW);
        } else {
            int gx = cnt < 1 ? 1 : cnt;
            k_small<<<dim3(gx, 4), 256>>>(d, left, right, (const float4*)W, bW);
        }
    }

    k_logits<<<(NNODES * 32 + 255) / 256, 256>>>((const float4*)P, bP, out);
}